// round 5
// baseline (speedup 1.0000x reference)
#include <cuda_runtime.h>
#include <cstddef>

// Problem constants (fixed by the reference)
#define NN 50000
#define EE 800000
#define IND 256
#define HID 128
#define NBLK 196          // ceil(NN/256)

// ---------------- scratch (no allocation allowed) ----------------
__device__ int   g_is64;          // 1 if edge_index is int64, 0 if int32
__device__ float g_deg[NN];
__device__ float g_dinv[NN];
__device__ float g_dinv2[NN];
__device__ int   g_cnt[NN];
__device__ int   g_fillpos[NN];
__device__ int   g_rowptr[NN + 1];
__device__ int   g_bsum[256];
__device__ int   g_col[EE];
__device__ float g_w[EE];
__device__ __align__(16) float g_h1[(size_t)NN * HID];  // GEMM output (reused by both layers)
__device__ __align__(16) float g_a1[(size_t)NN * HID];  // layer-1 aggregated output

// Read src/dst of edge e under either dtype layout.
// int32 layout: [2,E] int32 -> src = p[e],   dst = p[E+e]
// int64 layout: [2,E] int64 -> src = p[2e] (low word), dst = p[2(E+e)]
__device__ __forceinline__ int edge_src(const int* p, int e, int is64) {
    return is64 ? p[2 * e] : p[e];
}
__device__ __forceinline__ int edge_dst(const int* p, int e, int is64) {
    return is64 ? p[2 * (EE + e)] : p[EE + e];
}

// ---------------- dtype detector ----------------
// If edge_index is int64 (values < 2^31), every odd int32 word is 0.
// If int32, odd words are random node ids (nonzero w.p. 1 - 1/50000 each).
__global__ void detect_kernel(const int* __restrict__ ei) {
    __shared__ int nz;
    if (threadIdx.x == 0) nz = 0;
    __syncthreads();
    int v = ei[2 * threadIdx.x + 1];   // first 512 ints: in-bounds for both layouts
    if (v != 0) atomicAdd(&nz, 1);
    __syncthreads();
    if (threadIdx.x == 0) g_is64 = (nz < 8) ? 1 : 0;
}

// ---------------- shuffle-based inclusive block scan (256 threads) ----------------
__device__ __forceinline__ int block_incl_scan(int v, int* warp_sums) {
    int lane = threadIdx.x & 31;
    int wid = threadIdx.x >> 5;
#pragma unroll
    for (int d = 1; d < 32; d <<= 1) {
        int n = __shfl_up_sync(0xFFFFFFFFu, v, d);
        if (lane >= d) v += n;
    }
    if (lane == 31) warp_sums[wid] = v;
    __syncthreads();
    if (wid == 0) {
        int s = (lane < 8) ? warp_sums[lane] : 0;
#pragma unroll
        for (int d = 1; d < 8; d <<= 1) {
            int n = __shfl_up_sync(0xFFFFFFFFu, s, d);
            if (lane >= d) s += n;
        }
        if (lane < 8) warp_sums[lane] = s;
    }
    __syncthreads();
    int off = (wid > 0) ? warp_sums[wid - 1] : 0;
    return v + off;
}

// ---------------- graph preprocessing ----------------
__global__ void init_kernel() {
    int i = blockIdx.x * blockDim.x + threadIdx.x;
    if (i < NN) {
        g_deg[i] = 1.0f;   // self-loop weight
        g_cnt[i] = 0;
        g_fillpos[i] = 0;
    }
    if (i == 0) g_rowptr[0] = 0;
}

__global__ void count_kernel(const int* __restrict__ ei,
                             const float* __restrict__ ew) {
    int e = blockIdx.x * blockDim.x + threadIdx.x;
    if (e < EE) {
        const int is64 = g_is64;
        int d = edge_dst(ei, e, is64);
        if ((unsigned)d < NN) {          // bounds guard: never trap on bad data
            atomicAdd(&g_deg[d], ew[e]);
            atomicAdd(&g_cnt[d], 1);
        }
    }
}

__global__ void dinv_kernel() {
    int i = blockIdx.x * blockDim.x + threadIdx.x;
    if (i < NN) {
        float dv = rsqrtf(g_deg[i]);
        g_dinv[i] = dv;
        g_dinv2[i] = dv * dv;
    }
}

__global__ void scan1_kernel() {
    __shared__ int warp_sums[8];
    int gid = blockIdx.x * 256 + threadIdx.x;
    int v = (gid < NN) ? g_cnt[gid] : 0;
    int incl = block_incl_scan(v, warp_sums);
    if (gid < NN) g_rowptr[gid + 1] = incl;
    if (threadIdx.x == 255) g_bsum[blockIdx.x] = incl;  // block total
}

__global__ void scan2_kernel() {
    __shared__ int warp_sums[8];
    int tid = threadIdx.x;
    int v = (tid < NBLK) ? g_bsum[tid] : 0;
    int incl = block_incl_scan(v, warp_sums);
    if (tid < NBLK) g_bsum[tid] = incl - v;   // exclusive block offsets
}

__global__ void scan3_kernel() {
    int gid = blockIdx.x * 256 + threadIdx.x;
    int off = g_bsum[blockIdx.x];
    if (gid < NN) g_rowptr[gid + 1] += off;
}

__global__ void fill_kernel(const int* __restrict__ ei,
                            const float* __restrict__ ew) {
    int e = blockIdx.x * blockDim.x + threadIdx.x;
    if (e < EE) {
        const int is64 = g_is64;
        int s = edge_src(ei, e, is64);
        int d = edge_dst(ei, e, is64);
        if ((unsigned)s < NN && (unsigned)d < NN) {
            int pos = g_rowptr[d] + atomicAdd(&g_fillpos[d], 1);
            g_col[pos] = s;
            g_w[pos] = g_dinv[s] * ew[e] * g_dinv[d];
        }
    }
}

// ---------------- GEMM: C[NN x 128] = A[NN x K] @ B[K x 128] ----------------
template <int K>
__global__ void gemm_kernel(const float* __restrict__ Aext,
                            const float* __restrict__ B, int nrows) {
    constexpr int BM = 64, BN = 128, BK = 8;
    const float* A = (K == IND) ? Aext : g_a1;
    float* C = g_h1;

    __shared__ float As[BK][BM];
    __shared__ float Bs[BK][BN];

    int tid = threadIdx.x;
    int tx = tid & 31;   // 32 col groups of 4
    int ty = tid >> 5;   // 8 row groups of 8
    int row0 = blockIdx.x * BM;

    float acc[8][4];
#pragma unroll
    for (int i = 0; i < 8; i++)
#pragma unroll
        for (int j = 0; j < 4; j++) acc[i][j] = 0.0f;

    int a_row = tid >> 2;         // 0..63
    int a_k = (tid & 3) * 2;      // 0,2,4,6
    int b_kk = tid >> 5;          // 0..7
    int b_col = (tid & 31) * 4;

    for (int k0 = 0; k0 < K; k0 += BK) {
        int gr = row0 + a_row;
        float a0 = 0.0f, a1 = 0.0f;
        if (gr < nrows) {
            const float* ap = A + (size_t)gr * K + k0 + a_k;
            a0 = ap[0];
            a1 = ap[1];
        }
        As[a_k][a_row] = a0;
        As[a_k + 1][a_row] = a1;

        const float* bp = B + (size_t)(k0 + b_kk) * BN + b_col;
        Bs[b_kk][b_col + 0] = bp[0];
        Bs[b_kk][b_col + 1] = bp[1];
        Bs[b_kk][b_col + 2] = bp[2];
        Bs[b_kk][b_col + 3] = bp[3];
        __syncthreads();

#pragma unroll
        for (int kk = 0; kk < BK; kk++) {
            float b0 = Bs[kk][tx * 4 + 0];
            float b1 = Bs[kk][tx * 4 + 1];
            float b2 = Bs[kk][tx * 4 + 2];
            float b3 = Bs[kk][tx * 4 + 3];
#pragma unroll
            for (int i = 0; i < 8; i++) {
                float a = As[kk][ty * 8 + i];
                acc[i][0] += a * b0;
                acc[i][1] += a * b1;
                acc[i][2] += a * b2;
                acc[i][3] += a * b3;
            }
        }
        __syncthreads();
    }

#pragma unroll
    for (int i = 0; i < 8; i++) {
        int r = row0 + ty * 8 + i;
        if (r < nrows) {
            float4 v = make_float4(acc[i][0], acc[i][1], acc[i][2], acc[i][3]);
            *(float4*)(C + (size_t)r * BN + tx * 4) = v;  // own aligned global
        }
    }
}

// ---------------- aggregation: one warp per node, 2-deep SW pipeline ----------------
template <int HEAD>
__global__ void agg_kernel_t(const float* __restrict__ bias,
                             const float* __restrict__ Wc,
                             const float* __restrict__ bc,
                             float* __restrict__ out) {
    int warp = (blockIdx.x * blockDim.x + threadIdx.x) >> 5;
    int lane = threadIdx.x & 31;
    if (warp >= NN) return;

    const float4* __restrict__ hp = (const float4*)g_h1;
    float d2 = g_dinv2[warp];
    float4 self = hp[(size_t)warp * 32 + lane];
    float4 acc0 = make_float4(self.x * d2, self.y * d2, self.z * d2, self.w * d2);
    float4 acc1 = make_float4(0.f, 0.f, 0.f, 0.f);

    int beg = g_rowptr[warp], end = g_rowptr[warp + 1];
    int n = end - beg;

    int e = beg;
    if (n >= 2) {
        int   c0 = g_col[e],     c1 = g_col[e + 1];
        float w0 = g_w[e],       w1 = g_w[e + 1];
        for (; e + 3 < end; e += 2) {
            float4 v0 = hp[(size_t)c0 * 32 + lane];
            float4 v1 = hp[(size_t)c1 * 32 + lane];
            int   nc0 = g_col[e + 2], nc1 = g_col[e + 3];
            float nw0 = g_w[e + 2],   nw1 = g_w[e + 3];
            acc0.x += v0.x * w0; acc0.y += v0.y * w0;
            acc0.z += v0.z * w0; acc0.w += v0.w * w0;
            acc1.x += v1.x * w1; acc1.y += v1.y * w1;
            acc1.z += v1.z * w1; acc1.w += v1.w * w1;
            c0 = nc0; c1 = nc1; w0 = nw0; w1 = nw1;
        }
        float4 v0 = hp[(size_t)c0 * 32 + lane];
        float4 v1 = hp[(size_t)c1 * 32 + lane];
        acc0.x += v0.x * w0; acc0.y += v0.y * w0;
        acc0.z += v0.z * w0; acc0.w += v0.w * w0;
        acc1.x += v1.x * w1; acc1.y += v1.y * w1;
        acc1.z += v1.z * w1; acc1.w += v1.w * w1;
        e += 2;
    }
    for (; e < end; e++) {
        int c = g_col[e];
        float w = g_w[e];
        float4 v = hp[(size_t)c * 32 + lane];
        acc0.x += v.x * w; acc0.y += v.y * w;
        acc0.z += v.z * w; acc0.w += v.w * w;
    }

    acc0.x += acc1.x + bias[lane * 4 + 0];
    acc0.y += acc1.y + bias[lane * 4 + 1];
    acc0.z += acc1.z + bias[lane * 4 + 2];
    acc0.w += acc1.w + bias[lane * 4 + 3];

    if (HEAD == 0) {
        ((float4*)g_a1)[(size_t)warp * 32 + lane] = acc0;
    } else {
        float p = acc0.x * Wc[lane * 4 + 0] + acc0.y * Wc[lane * 4 + 1]
                + acc0.z * Wc[lane * 4 + 2] + acc0.w * Wc[lane * 4 + 3];
#pragma unroll
        for (int off = 16; off > 0; off >>= 1)
            p += __shfl_xor_sync(0xFFFFFFFFu, p, off);
        if (lane == 0) out[warp] = p + bc[0];
    }
}

// ---------------- launch ----------------
extern "C" void kernel_launch(void* const* d_in, const int* in_sizes, int n_in,
                              void* d_out, int out_size) {
    const float* x       = (const float*)d_in[0];
    const int*   ei      = (const int*)d_in[1];   // int32 OR int64 (detected on device)
    const float* ew      = (const float*)d_in[2];
    const float* W1      = (const float*)d_in[3];
    const float* b1      = (const float*)d_in[4];
    const float* W2      = (const float*)d_in[5];
    const float* b2      = (const float*)d_in[6];
    const float* Wc      = (const float*)d_in[7];
    const float* bc      = (const float*)d_in[8];
    float* out           = (float*)d_out;

    const int TB = 256;
    const int AGGTB = 512;                     // 16 warps/block for agg
    const int nb_n = (NN + TB - 1) / TB;
    const int nb_e = (EE + TB - 1) / TB;
    const int nb_g = (NN + 63) / 64;           // GEMM blocks (BM=64)
    const int nb_a = (NN + 15) / 16;           // agg blocks (16 warps/block)

    // dtype probe + graph preprocessing (CSR by dst, symmetric-normalized weights)
    detect_kernel<<<1, 256>>>(ei);
    init_kernel<<<nb_n, TB>>>();
    count_kernel<<<nb_e, TB>>>(ei, ew);
    dinv_kernel<<<nb_n, TB>>>();
    scan1_kernel<<<NBLK, TB>>>();
    scan2_kernel<<<1, TB>>>();
    scan3_kernel<<<NBLK, TB>>>();
    fill_kernel<<<nb_e, TB>>>(ei, ew);

    // layer 1: h1 = x@W1 ; a1 = agg(h1) + h1*dinv2 + b1
    gemm_kernel<IND><<<nb_g, TB>>>(x, W1, NN);
    agg_kernel_t<0><<<nb_a, AGGTB>>>(b1, nullptr, nullptr, nullptr);

    // layer 2 + head: h2 = a1@W2 ; out = (agg(h2) + h2*dinv2 + b2) . Wc + bc
    gemm_kernel<HID><<<nb_g, TB>>>(nullptr, W2, NN);
    agg_kernel_t<1><<<nb_a, AGGTB>>>(b2, Wc, bc, out);
}

// round 7
// speedup vs baseline: 3.5360x; 3.5360x over previous
#include <cuda_runtime.h>
#include <cstddef>

// Problem constants (fixed by the reference)
#define NN 50000
#define EE 800000
#define IND 256
#define HID 128

// ---------------- scratch (no allocation allowed) ----------------
__device__ int   g_is64;          // 1 if edge_index is int64, 0 if int32
__device__ float g_deg[NN];
__device__ float g_dinv[NN];
__device__ float g_dinv2[NN];
__device__ float g_t[NN];         // t = x @ u
__device__ float g_s[NN];         // layer-1 collapsed output
__device__ float g_z[NN];         // layer-2 scatter accumulator
__device__ float g_v[HID];        // v = W2 @ Wc
__device__ float g_u[IND];        // u = W1 @ v
__device__ float g_b1v;           // b1 . v
__device__ float g_b2c;           // b2 . Wc + bc

// Read src/dst of edge e under either dtype layout.
// int32 layout: [2,E] int32 -> src = p[e],   dst = p[E+e]
// int64 layout: [2,E] int64 -> src = p[2e] (low word), dst = p[2(E+e)]
__device__ __forceinline__ int edge_src(const int* p, int e, int is64) {
    return is64 ? p[2 * e] : p[e];
}
__device__ __forceinline__ int edge_dst(const int* p, int e, int is64) {
    return is64 ? p[2 * (EE + e)] : p[EE + e];
}

// ---------------- init + dtype probe (block 0 does the probe) ----------------
// If edge_index is int64 (values < 2^31), every odd int32 word is 0.
// If int32, odd words are random node ids (nonzero w.p. 1 - 1/50000 each).
__global__ void init_kernel(const int* __restrict__ ei) {
    int i = blockIdx.x * blockDim.x + threadIdx.x;
    if (i < NN) {
        g_deg[i] = 1.0f;   // self-loop weight
        g_s[i] = 0.0f;
        g_z[i] = 0.0f;
    }
    if (blockIdx.x == 0) {
        __shared__ int nz;
        if (threadIdx.x == 0) nz = 0;
        __syncthreads();
        int v = ei[2 * threadIdx.x + 1];   // first 512 ints: in-bounds for both layouts
        if (v != 0) atomicAdd(&nz, 1);
        __syncthreads();
        if (threadIdx.x == 0) g_is64 = (nz < 8) ? 1 : 0;
    }
}

// ---------------- degree scatter ----------------
__global__ void deg_kernel(const int* __restrict__ ei,
                           const float* __restrict__ ew) {
    int e = blockIdx.x * blockDim.x + threadIdx.x;
    if (e < EE) {
        int d = edge_dst(ei, e, g_is64);
        if ((unsigned)d < NN) atomicAdd(&g_deg[d], ew[e]);
    }
}

__global__ void dinv_kernel() {
    int i = blockIdx.x * blockDim.x + threadIdx.x;
    if (i < NN) {
        float dv = rsqrtf(g_deg[i]);
        g_dinv[i] = dv;
        g_dinv2[i] = dv * dv;
    }
}

// ---------------- collapse the weights: v = W2@Wc, u = W1@v, scalars ----------------
// Single block, 256 threads. Tiny (~50K FMA).
__global__ void weights_kernel(const float* __restrict__ W1,
                               const float* __restrict__ b1,
                               const float* __restrict__ W2,
                               const float* __restrict__ b2,
                               const float* __restrict__ Wc,
                               const float* __restrict__ bc) {
    __shared__ float sv[HID];
    int tid = threadIdx.x;
    if (tid < HID) {
        float acc = 0.0f;
        for (int k = 0; k < HID; k++) acc += W2[tid * HID + k] * Wc[k];
        sv[tid] = acc;
        g_v[tid] = acc;
    }
    __syncthreads();
    {
        float acc = 0.0f;
        for (int j = 0; j < HID; j++) acc += W1[tid * HID + j] * sv[j];
        g_u[tid] = acc;   // tid covers all 256 rows of W1
    }
    if (tid == 0) {
        float a = 0.0f, b = 0.0f;
        for (int j = 0; j < HID; j++) a += b1[j] * sv[j];
        for (int k = 0; k < HID; k++) b += b2[k] * Wc[k];
        g_b1v = a;
        g_b2c = b + bc[0];
    }
}

// ---------------- GEMV: t = x @ u  (one warp per row, coalesced float4) ----------------
__global__ void gemv_kernel(const float* __restrict__ x) {
    __shared__ float su[IND];
    int tid = threadIdx.x;
    su[tid] = g_u[tid];            // blockDim.x == 256 == IND
    __syncthreads();

    int warp = blockIdx.x * 8 + (tid >> 5);
    int lane = tid & 31;
    if (warp >= NN) return;

    const float4* xp = (const float4*)(x + (size_t)warp * IND);
    float acc = 0.0f;
#pragma unroll
    for (int i = 0; i < 2; i++) {
        int c = lane + i * 32;          // float4 index 0..63
        float4 xv = xp[c];
        acc += xv.x * su[c * 4 + 0] + xv.y * su[c * 4 + 1]
             + xv.z * su[c * 4 + 2] + xv.w * su[c * 4 + 3];
    }
#pragma unroll
    for (int off = 16; off > 0; off >>= 1)
        acc += __shfl_xor_sync(0xFFFFFFFFu, acc, off);
    if (lane == 0) g_t[warp] = acc;
}

// ---------------- scalar edge scatter: dstbuf[d] += srcbuf[s] * norm ----------------
template <int PASS>   // PASS=1: g_t -> g_s ; PASS=2: g_s -> g_z
__global__ void scatter_kernel(const int* __restrict__ ei,
                               const float* __restrict__ ew) {
    int e = blockIdx.x * blockDim.x + threadIdx.x;
    if (e < EE) {
        const int is64 = g_is64;
        int s = edge_src(ei, e, is64);
        int d = edge_dst(ei, e, is64);
        if ((unsigned)s < NN && (unsigned)d < NN) {
            float norm = g_dinv[s] * ew[e] * g_dinv[d];
            if (PASS == 1) atomicAdd(&g_s[d], g_t[s] * norm);
            else           atomicAdd(&g_z[d], g_s[s] * norm);
        }
    }
}

// ---------------- finalizers: add self-loop term + collapsed bias ----------------
__global__ void fin1_kernel() {
    int i = blockIdx.x * blockDim.x + threadIdx.x;
    if (i < NN) g_s[i] = g_s[i] + g_t[i] * g_dinv2[i] + g_b1v;
}

__global__ void fin2_kernel(float* __restrict__ out) {
    int i = blockIdx.x * blockDim.x + threadIdx.x;
    if (i < NN) out[i] = g_z[i] + g_s[i] * g_dinv2[i] + g_b2c;
}

// ---------------- launch ----------------
extern "C" void kernel_launch(void* const* d_in, const int* in_sizes, int n_in,
                              void* d_out, int out_size) {
    const float* x  = (const float*)d_in[0];
    const int*   ei = (const int*)d_in[1];   // int32 OR int64 (detected on device)
    const float* ew = (const float*)d_in[2];
    const float* W1 = (const float*)d_in[3];
    const float* b1 = (const float*)d_in[4];
    const float* W2 = (const float*)d_in[5];
    const float* b2 = (const float*)d_in[6];
    const float* Wc = (const float*)d_in[7];
    const float* bc = (const float*)d_in[8];
    float* out      = (float*)d_out;

    const int TB = 256;
    const int nb_n = (NN + TB - 1) / TB;
    const int nb_e = (EE + TB - 1) / TB;
    const int nb_g = (NN + 7) / 8;           // gemv: 8 warps (rows) per block

    init_kernel<<<nb_n, TB>>>(ei);           // also probes dtype (block 0)
    deg_kernel<<<nb_e, TB>>>(ei, ew);
    dinv_kernel<<<nb_n, TB>>>();
    weights_kernel<<<1, 256>>>(W1, b1, W2, b2, Wc, bc);

    // t = x @ (W1 @ W2 @ Wc)
    gemv_kernel<<<nb_g, TB>>>(x);

    // layer 1 (collapsed to scalars): s = scatter(t) + t*dinv2 + b1.v
    scatter_kernel<1><<<nb_e, TB>>>(ei, ew);
    fin1_kernel<<<nb_n, TB>>>();

    // layer 2 + head: out = scatter(s) + s*dinv2 + (b2.Wc + bc)
    scatter_kernel<2><<<nb_e, TB>>>(ei, ew);
    fin2_kernel<<<nb_n, TB>>>(out);
}

// round 8
// speedup vs baseline: 5.3684x; 1.5182x over previous
#include <cuda_runtime.h>
#include <cstddef>

// Problem constants (fixed by the reference)
#define NN 50000
#define EE 800000
#define IND 256
#define HID 128

// ---------------- scratch (no allocation allowed) ----------------
__device__ int   g_is64;          // 1 if edge_index is int64, 0 if int32
__device__ float g_deg[NN];
__device__ float g_dinv[NN];
__device__ float g_dinv2[NN];
__device__ float g_t[NN];         // t = x @ u
__device__ float g_s[NN];         // layer-1 collapsed output
__device__ float g_z[NN];         // layer-2 scatter accumulator
__device__ float g_v[HID];        // v = W2 @ Wc
__device__ float g_u[IND];        // u = W1 @ v
__device__ float g_b1v;           // b1 . v
__device__ float g_b2c;           // b2 . Wc + bc

// Read src/dst of edge e under either dtype layout.
// int32 layout: [2,E] int32 -> src = p[e],   dst = p[E+e]
// int64 layout: [2,E] int64 -> src = p[2e] (low word), dst = p[2(E+e)]
__device__ __forceinline__ int edge_src(const int* p, int e, int is64) {
    return is64 ? p[2 * e] : p[e];
}
__device__ __forceinline__ int edge_dst(const int* p, int e, int is64) {
    return is64 ? p[2 * (EE + e)] : p[EE + e];
}

__device__ __forceinline__ float warp_reduce(float v) {
#pragma unroll
    for (int off = 16; off > 0; off >>= 1)
        v += __shfl_xor_sync(0xFFFFFFFFu, v, off);
    return v;
}

// ---------------- init + dtype probe (block 0 does the probe) ----------------
__global__ void init_kernel(const int* __restrict__ ei) {
    int i = blockIdx.x * blockDim.x + threadIdx.x;
    if (i < NN) {
        g_deg[i] = 1.0f;   // self-loop weight
        g_s[i] = 0.0f;
        g_z[i] = 0.0f;
    }
    if (blockIdx.x == 0) {
        __shared__ int nz;
        if (threadIdx.x == 0) nz = 0;
        __syncthreads();
        int v = ei[2 * threadIdx.x + 1];   // first 512 ints: in-bounds for both layouts
        if (v != 0) atomicAdd(&nz, 1);
        __syncthreads();
        if (threadIdx.x == 0) g_is64 = (nz < 8) ? 1 : 0;
    }
}

// ---------------- degree scatter ----------------
__global__ void deg_kernel(const int* __restrict__ ei,
                           const float* __restrict__ ew) {
    int e = blockIdx.x * blockDim.x + threadIdx.x;
    if (e < EE) {
        int d = edge_dst(ei, e, g_is64);
        if ((unsigned)d < NN) atomicAdd(&g_deg[d], ew[e]);
    }
}

__global__ void dinv_kernel() {
    int i = blockIdx.x * blockDim.x + threadIdx.x;
    if (i < NN) {
        float dv = rsqrtf(g_deg[i]);
        g_dinv[i] = dv;
        g_dinv2[i] = dv * dv;
    }
}

// ---------------- weight collapse, stage 1: v = W2 @ Wc  (warp per row) ----------------
// grid: 17 blocks x 256 threads = 136 warps; warps 0..127 rows, warp 128 scalars.
__global__ void weights1_kernel(const float* __restrict__ W2,
                                const float* __restrict__ Wc,
                                const float* __restrict__ b2,
                                const float* __restrict__ bc) {
    int warp = blockIdx.x * 8 + (threadIdx.x >> 5);
    int lane = threadIdx.x & 31;
    if (warp < HID) {
        const float* row = W2 + (size_t)warp * HID;
        float acc = 0.0f;
#pragma unroll
        for (int i = 0; i < 4; i++) {
            int k = lane + i * 32;
            acc += row[k] * Wc[k];
        }
        acc = warp_reduce(acc);
        if (lane == 0) g_v[warp] = acc;
    } else if (warp == HID) {
        float acc = 0.0f;
#pragma unroll
        for (int i = 0; i < 4; i++) {
            int k = lane + i * 32;
            acc += b2[k] * Wc[k];
        }
        acc = warp_reduce(acc);
        if (lane == 0) g_b2c = acc + bc[0];
    }
}

// ---------------- weight collapse, stage 2: u = W1 @ v  (warp per row) ----------------
// grid: 33 blocks x 256 threads = 264 warps; warps 0..255 rows, warp 256 b1.v.
__global__ void weights2_kernel(const float* __restrict__ W1,
                                const float* __restrict__ b1) {
    int warp = blockIdx.x * 8 + (threadIdx.x >> 5);
    int lane = threadIdx.x & 31;
    if (warp < IND) {
        const float* row = W1 + (size_t)warp * HID;
        float acc = 0.0f;
#pragma unroll
        for (int i = 0; i < 4; i++) {
            int k = lane + i * 32;
            acc += row[k] * g_v[k];
        }
        acc = warp_reduce(acc);
        if (lane == 0) g_u[warp] = acc;
    } else if (warp == IND) {
        float acc = 0.0f;
#pragma unroll
        for (int i = 0; i < 4; i++) {
            int k = lane + i * 32;
            acc += b1[k] * g_v[k];
        }
        acc = warp_reduce(acc);
        if (lane == 0) g_b1v = acc;
    }
}

// ---------------- GEMV: t = x @ u  (one warp per row, coalesced float4) ----------------
__global__ void gemv_kernel(const float* __restrict__ x) {
    __shared__ float su[IND];
    int tid = threadIdx.x;
    su[tid] = g_u[tid];            // blockDim.x == 256 == IND
    __syncthreads();

    int warp = blockIdx.x * 8 + (tid >> 5);
    int lane = tid & 31;
    if (warp >= NN) return;

    const float4* xp = (const float4*)(x + (size_t)warp * IND);
    float acc = 0.0f;
#pragma unroll
    for (int i = 0; i < 2; i++) {
        int c = lane + i * 32;          // float4 index 0..63
        float4 xv = xp[c];
        acc += xv.x * su[c * 4 + 0] + xv.y * su[c * 4 + 1]
             + xv.z * su[c * 4 + 2] + xv.w * su[c * 4 + 3];
    }
    acc = warp_reduce(acc);
    if (lane == 0) g_t[warp] = acc;
}

// ---------------- scalar edge scatter: dstbuf[d] += srcbuf[s] * norm ----------------
template <int PASS>   // PASS=1: g_t -> g_s ; PASS=2: g_s -> g_z
__global__ void scatter_kernel(const int* __restrict__ ei,
                               const float* __restrict__ ew) {
    int e = blockIdx.x * blockDim.x + threadIdx.x;
    if (e < EE) {
        const int is64 = g_is64;
        int s = edge_src(ei, e, is64);
        int d = edge_dst(ei, e, is64);
        if ((unsigned)s < NN && (unsigned)d < NN) {
            float norm = g_dinv[s] * ew[e] * g_dinv[d];
            if (PASS == 1) atomicAdd(&g_s[d], g_t[s] * norm);
            else           atomicAdd(&g_z[d], g_s[s] * norm);
        }
    }
}

// ---------------- finalizers: add self-loop term + collapsed bias ----------------
__global__ void fin1_kernel() {
    int i = blockIdx.x * blockDim.x + threadIdx.x;
    if (i < NN) g_s[i] = g_s[i] + g_t[i] * g_dinv2[i] + g_b1v;
}

__global__ void fin2_kernel(float* __restrict__ out) {
    int i = blockIdx.x * blockDim.x + threadIdx.x;
    if (i < NN) out[i] = g_z[i] + g_s[i] * g_dinv2[i] + g_b2c;
}

// ---------------- launch ----------------
extern "C" void kernel_launch(void* const* d_in, const int* in_sizes, int n_in,
                              void* d_out, int out_size) {
    const float* x  = (const float*)d_in[0];
    const int*   ei = (const int*)d_in[1];   // int32 OR int64 (detected on device)
    const float* ew = (const float*)d_in[2];
    const float* W1 = (const float*)d_in[3];
    const float* b1 = (const float*)d_in[4];
    const float* W2 = (const float*)d_in[5];
    const float* b2 = (const float*)d_in[6];
    const float* Wc = (const float*)d_in[7];
    const float* bc = (const float*)d_in[8];
    float* out      = (float*)d_out;

    const int TB = 256;
    const int nb_n = (NN + TB - 1) / TB;
    const int nb_e = (EE + TB - 1) / TB;
    const int nb_g = (NN + 7) / 8;           // gemv: 8 warps (rows) per block

    init_kernel<<<nb_n, TB>>>(ei);           // also probes dtype (block 0)
    weights1_kernel<<<17, TB>>>(W2, Wc, b2, bc);
    weights2_kernel<<<33, TB>>>(W1, b1);
    deg_kernel<<<nb_e, TB>>>(ei, ew);
    dinv_kernel<<<nb_n, TB>>>();

    // t = x @ (W1 @ W2 @ Wc)
    gemv_kernel<<<nb_g, TB>>>(x);

    // layer 1 (collapsed to scalars): s = scatter(t) + t*dinv2 + b1.v
    scatter_kernel<1><<<nb_e, TB>>>(ei, ew);
    fin1_kernel<<<nb_n, TB>>>();

    // layer 2 + head: out = scatter(s) + s*dinv2 + (b2.Wc + bc)
    scatter_kernel<2><<<nb_e, TB>>>(ei, ew);
    fin2_kernel<<<nb_n, TB>>>(out);
}

// round 10
// speedup vs baseline: 6.3014x; 1.1738x over previous
#include <cuda_runtime.h>
#include <cstddef>

// Problem constants (fixed by the reference)
#define NN 50000
#define EE 800000
#define IND 256
#define HID 128
#define NE4 ((EE / 4 + 255) / 256)   // 782 blocks, 4 edges/thread (EE % 4 == 0)
#define NBG ((NN + 7) / 8)           // 6250 gemv blocks, 8 rows/block

// ---------------- scratch (no allocation allowed) ----------------
__device__ int   g_is64;          // 1 if edge_index is int64, 0 if int32
__device__ float g_deg[NN];
__device__ float g_dinv[NN];
__device__ float g_t[NN];         // t = x @ u  (raw)
__device__ float g_tt[NN];        // tt = dinv * t
__device__ float g_s[NN];         // scatter1 accumulator (raw)
__device__ float g_ss[NN];        // ss = dinv * s_final
__device__ float g_z[NN];         // scatter2 accumulator (raw)
__device__ float g_v[HID];        // v = W2 @ Wc
__device__ float g_u[IND];        // u = W1 @ v
__device__ float g_b1v;           // b1 . v
__device__ float g_b2c;           // b2 . Wc + bc

__device__ __forceinline__ int edge_src64(const int* p, int e) { return p[2 * e]; }
__device__ __forceinline__ int edge_dst64(const int* p, int e) { return p[2 * (EE + e)]; }

__device__ __forceinline__ float warp_reduce(float v) {
#pragma unroll
    for (int off = 16; off > 0; off >>= 1)
        v += __shfl_xor_sync(0xFFFFFFFFu, v, off);
    return v;
}

// ---------------- init + dtype probe (block 0) ----------------
__global__ void init_kernel(const int* __restrict__ ei) {
    int i = blockIdx.x * blockDim.x + threadIdx.x;
    if (i < NN) {
        g_deg[i] = 1.0f;   // self-loop weight
        g_s[i] = 0.0f;
        g_z[i] = 0.0f;
    }
    if (blockIdx.x == 0) {
        __shared__ int nz;
        if (threadIdx.x == 0) nz = 0;
        __syncthreads();
        int v = ei[2 * threadIdx.x + 1];   // odd words: 0 iff int64 layout
        if (v != 0) atomicAdd(&nz, 1);
        __syncthreads();
        if (threadIdx.x == 0) g_is64 = (nz < 8) ? 1 : 0;
    }
}

// ---------------- weight collapse stage 1: v = W2 @ Wc (warp/row) ----------------
__global__ void weights1_kernel(const float* __restrict__ W2,
                                const float* __restrict__ Wc,
                                const float* __restrict__ b2,
                                const float* __restrict__ bc) {
    int warp = blockIdx.x * 8 + (threadIdx.x >> 5);
    int lane = threadIdx.x & 31;
    if (warp < HID) {
        const float* row = W2 + (size_t)warp * HID;
        float acc = 0.0f;
#pragma unroll
        for (int i = 0; i < 4; i++) { int k = lane + i * 32; acc += row[k] * Wc[k]; }
        acc = warp_reduce(acc);
        if (lane == 0) g_v[warp] = acc;
    } else if (warp == HID) {
        float acc = 0.0f;
#pragma unroll
        for (int i = 0; i < 4; i++) { int k = lane + i * 32; acc += b2[k] * Wc[k]; }
        acc = warp_reduce(acc);
        if (lane == 0) g_b2c = acc + bc[0];
    }
}

// ---------------- weight collapse stage 2: u = W1 @ v (warp/row) ----------------
__global__ void weights2_kernel(const float* __restrict__ W1,
                                const float* __restrict__ b1) {
    int warp = blockIdx.x * 8 + (threadIdx.x >> 5);
    int lane = threadIdx.x & 31;
    if (warp < IND) {
        const float* row = W1 + (size_t)warp * HID;
        float acc = 0.0f;
#pragma unroll
        for (int i = 0; i < 4; i++) { int k = lane + i * 32; acc += row[k] * g_v[k]; }
        acc = warp_reduce(acc);
        if (lane == 0) g_u[warp] = acc;
    } else if (warp == IND) {
        float acc = 0.0f;
#pragma unroll
        for (int i = 0; i < 4; i++) { int k = lane + i * 32; acc += b1[k] * g_v[k]; }
        acc = warp_reduce(acc);
        if (lane == 0) g_b1v = acc;
    }
}

// ---------------- fused: degree scatter (blocks < NE4) + GEMV t = x@u ----------------
// Disjoint outputs: deg blocks write g_deg, gemv blocks write g_t. No ordering needed.
__global__ void deg_gemv_kernel(const int* __restrict__ ei,
                                const float* __restrict__ ew,
                                const float* __restrict__ x) {
    if (blockIdx.x < NE4) {
        // 4 edges per thread, vectorized when int32 layout
        int idx = blockIdx.x * 256 + threadIdx.x;
        if (idx >= EE / 4) return;
        int e4 = idx * 4;
        float4 w4 = *(const float4*)(ew + e4);
        if (g_is64 == 0) {
            int4 d4 = *(const int4*)(ei + EE + e4);
            if ((unsigned)d4.x < NN) atomicAdd(&g_deg[d4.x], w4.x);
            if ((unsigned)d4.y < NN) atomicAdd(&g_deg[d4.y], w4.y);
            if ((unsigned)d4.z < NN) atomicAdd(&g_deg[d4.z], w4.z);
            if ((unsigned)d4.w < NN) atomicAdd(&g_deg[d4.w], w4.w);
        } else {
            const float* wp = &w4.x;
#pragma unroll
            for (int j = 0; j < 4; j++) {
                int d = edge_dst64(ei, e4 + j);
                if ((unsigned)d < NN) atomicAdd(&g_deg[d], wp[j]);
            }
        }
    } else {
        // GEMV: one warp per row, coalesced float4 reads of x
        __shared__ float su[IND];
        int tid = threadIdx.x;
        su[tid] = g_u[tid];
        __syncthreads();

        int warp = (blockIdx.x - NE4) * 8 + (tid >> 5);
        int lane = tid & 31;
        if (warp >= NN) return;

        const float4* xp = (const float4*)(x + (size_t)warp * IND);
        float acc = 0.0f;
#pragma unroll
        for (int i = 0; i < 2; i++) {
            int c = lane + i * 32;
            float4 xv = xp[c];
            acc += xv.x * su[c * 4 + 0] + xv.y * su[c * 4 + 1]
                 + xv.z * su[c * 4 + 2] + xv.w * su[c * 4 + 3];
        }
        acc = warp_reduce(acc);
        if (lane == 0) g_t[warp] = acc;
    }
}

// ---------------- dinv + premultiply: dinv = rsqrt(deg), tt = t*dinv ----------------
__global__ void dinv_kernel() {
    int i = blockIdx.x * blockDim.x + threadIdx.x;
    if (i < NN) {
        float dv = rsqrtf(g_deg[i]);
        g_dinv[i] = dv;
        g_tt[i] = g_t[i] * dv;
    }
}

// ---------------- edge scatter: dst += ew * srcvec[src]  (4 edges/thread) ----------------
template <int PASS>   // PASS=1: g_tt -> g_s ; PASS=2: g_ss -> g_z
__global__ void scatter_kernel(const int* __restrict__ ei,
                               const float* __restrict__ ew) {
    int idx = blockIdx.x * 256 + threadIdx.x;
    if (idx >= EE / 4) return;
    int e4 = idx * 4;
    const float* srcvec = (PASS == 1) ? g_tt : g_ss;
    float* dstvec = (PASS == 1) ? g_s : g_z;
    float4 w4 = *(const float4*)(ew + e4);
    if (g_is64 == 0) {
        int4 s4 = *(const int4*)(ei + e4);
        int4 d4 = *(const int4*)(ei + EE + e4);
        if ((unsigned)s4.x < NN && (unsigned)d4.x < NN) atomicAdd(&dstvec[d4.x], w4.x * srcvec[s4.x]);
        if ((unsigned)s4.y < NN && (unsigned)d4.y < NN) atomicAdd(&dstvec[d4.y], w4.y * srcvec[s4.y]);
        if ((unsigned)s4.z < NN && (unsigned)d4.z < NN) atomicAdd(&dstvec[d4.z], w4.z * srcvec[s4.z]);
        if ((unsigned)s4.w < NN && (unsigned)d4.w < NN) atomicAdd(&dstvec[d4.w], w4.w * srcvec[s4.w]);
    } else {
        const float* wp = &w4.x;
#pragma unroll
        for (int j = 0; j < 4; j++) {
            int s = edge_src64(ei, e4 + j);
            int d = edge_dst64(ei, e4 + j);
            if ((unsigned)s < NN && (unsigned)d < NN)
                atomicAdd(&dstvec[d], wp[j] * srcvec[s]);
        }
    }
}

// ---------------- finalizers ----------------
// s_final = dinv*(s_raw + tt) + b1v ;  ss = dinv * s_final
__global__ void fin1_kernel() {
    int i = blockIdx.x * blockDim.x + threadIdx.x;
    if (i < NN) {
        float dv = g_dinv[i];
        float s = dv * (g_s[i] + g_tt[i]) + g_b1v;
        g_ss[i] = dv * s;
    }
}

// out = dinv*(z_raw + ss) + b2c
__global__ void fin2_kernel(float* __restrict__ out) {
    int i = blockIdx.x * blockDim.x + threadIdx.x;
    if (i < NN) out[i] = g_dinv[i] * (g_z[i] + g_ss[i]) + g_b2c;
}

// ---------------- launch ----------------
extern "C" void kernel_launch(void* const* d_in, const int* in_sizes, int n_in,
                              void* d_out, int out_size) {
    const float* x  = (const float*)d_in[0];
    const int*   ei = (const int*)d_in[1];   // int32 OR int64 (detected on device)
    const float* ew = (const float*)d_in[2];
    const float* W1 = (const float*)d_in[3];
    const float* b1 = (const float*)d_in[4];
    const float* W2 = (const float*)d_in[5];
    const float* b2 = (const float*)d_in[6];
    const float* Wc = (const float*)d_in[7];
    const float* bc = (const float*)d_in[8];
    float* out      = (float*)d_out;

    const int TB = 256;
    const int nb_n = (NN + TB - 1) / TB;

    init_kernel<<<nb_n, TB>>>(ei);                 // + dtype probe
    weights1_kernel<<<17, TB>>>(W2, Wc, b2, bc);   // v = W2@Wc, b2.Wc+bc
    weights2_kernel<<<33, TB>>>(W1, b1);           // u = W1@v,  b1.v

    // degree atomics overlapped with t = x@u (independent work, one kernel)
    deg_gemv_kernel<<<NE4 + NBG, TB>>>(ei, ew, x);
    dinv_kernel<<<nb_n, TB>>>();                   // dinv + tt = t*dinv

    // layer 1: s_raw[d] += ew * tt[src]; finalize -> ss
    scatter_kernel<1><<<NE4, TB>>>(ei, ew);
    fin1_kernel<<<nb_n, TB>>>();

    // layer 2 + head: z_raw[d] += ew * ss[src]; out = dinv*(z+ss) + b2c
    scatter_kernel<2><<<NE4, TB>>>(ei, ew);
    fin2_kernel<<<nb_n, TB>>>(out);
}